// round 1
// baseline (speedup 1.0000x reference)
#include <cuda_runtime.h>
#include <math.h>

// Problem constants
#define BB    4
#define KDIM  128
#define V_IN  256
#define E_IN  512
#define E_OUT 512
#define V_OUT 256
#define P_PE  200
#define T_PE  100
#define NROWS (BB*KDIM)        // 512
#define M_BIG (BB*KDIM*KDIM)   // 65536

// Scratch (device globals -- allocation-free per harness rules)
__device__ float g_v[NROWS*V_IN];
__device__ float g_q[NROWS*E_OUT];
__device__ float g_k[NROWS*E_OUT];
__device__ float g_self[NROWS*E_OUT];
__device__ float g_e[(size_t)M_BIG*E_IN];      // silu(epe)   134 MB
__device__ float g_h[(size_t)M_BIG*E_OUT];     // silu(ev1)   134 MB
__device__ float g_v2[NROWS*E_OUT];
__device__ float g_pool[BB*E_OUT];

__device__ __forceinline__ float siluf(float x){ return x / (1.f + __expf(-x)); }
__device__ __forceinline__ float sigmf(float x){ return 1.f / (1.f + __expf(-x)); }

// ---------------------------------------------------------------------------
// Kernel 1: v = silu([v_f, p_pe, t_pe] @ W_vpe + b)   (512 rows x 256, K=556)
// ---------------------------------------------------------------------------
__global__ void k_vpe(const float* __restrict__ v_f, const float* __restrict__ p_pe,
                      const float* __restrict__ t_pe, const float* __restrict__ W,
                      const float* __restrict__ bias)
{
    __shared__ float s_in[556];
    int m = blockIdx.x;       // 0..511
    int b = m >> 7;
    for (int kk = threadIdx.x; kk < 556; kk += 256) {
        float x;
        if      (kk < 256) x = v_f[m*256 + kk];
        else if (kk < 456) x = p_pe[m*200 + (kk-256)];
        else               x = t_pe[b*100 + (kk-456)];
        s_in[kk] = x;
    }
    __syncthreads();
    int n = threadIdx.x;      // 256 outputs
    float acc = bias[n];
    #pragma unroll 4
    for (int kk = 0; kk < 556; kk++) acc = fmaf(s_in[kk], W[kk*256 + n], acc);
    g_v[m*256 + n] = siluf(acc);
}

// ---------------------------------------------------------------------------
// Kernel 2: q = v@Wq+b, k = v@Wk+b, self = silu(v@Ws+b)  (512 rows, K=256, N=512 each)
// ---------------------------------------------------------------------------
__global__ void k_qks(const float* __restrict__ Wq, const float* __restrict__ bq,
                      const float* __restrict__ Wk, const float* __restrict__ bk,
                      const float* __restrict__ Ws, const float* __restrict__ bs)
{
    __shared__ float s_v[256];
    int m = blockIdx.x;
    for (int kk = threadIdx.x; kk < 256; kk += 512) s_v[kk] = g_v[m*256 + kk];
    __syncthreads();
    int n = threadIdx.x;      // 512
    float aq = bq[n], ak = bk[n], as_ = bs[n];
    #pragma unroll 4
    for (int kk = 0; kk < 256; kk++) {
        float x = s_v[kk];
        aq  = fmaf(x, Wq[kk*512 + n], aq);
        ak  = fmaf(x, Wk[kk*512 + n], ak);
        as_ = fmaf(x, Ws[kk*512 + n], as_);
    }
    g_q[m*512 + n]    = aq;
    g_k[m*512 + n]    = ak;
    g_self[m*512 + n] = siluf(as_);
}

// ---------------------------------------------------------------------------
// Big GEMM: C[M_BIG x 512] = act(gatherA @ W + bias)
// MODE 0 (epe): A = [e_f(512) | t_pe(100)], KD=612, silu, C=g_e
// MODE 1 (ev1): A = [v_i(256) | v_j(256) | g_e(512)], KD=1024, silu, C=g_h
// MODE 2 (ev2): A = g_h, KD=512, no act, C=Cout (e_value in d_out)
// Tiling: 64x64 block tile, BK=16, 256 threads, 4x4 per thread.
// ---------------------------------------------------------------------------
#define BM 64
#define BN 64
#define BK 16

template<int MODE>
__device__ __forceinline__ float loadA(int m, int kk,
                                       const float* __restrict__ A0,
                                       const float* __restrict__ A1)
{
    if (MODE == 0) {
        if (kk < 512) return A0[(size_t)m*512 + kk];
        int r = kk - 512;
        return (r < 100) ? A1[(m >> 14)*100 + r] : 0.f;   // guard KD=612 tile overrun
    } else if (MODE == 1) {
        int b = m >> 14, p = m & 16383;
        if (kk < 256) return g_v[((b<<7) + (p>>7))*256 + kk];
        if (kk < 512) return g_v[((b<<7) + (p&127))*256 + (kk-256)];
        return g_e[(size_t)m*512 + (kk-512)];
    } else {
        return g_h[(size_t)m*512 + kk];
    }
}

template<int MODE, int KD, bool DOSILU>
__global__ void gemm_big(const float* __restrict__ A0, const float* __restrict__ A1,
                         const float* __restrict__ W,  const float* __restrict__ bias,
                         float* __restrict__ Cout)
{
    __shared__ float As[BK][BM + 1];   // +1 pad: avoid STS bank conflicts
    __shared__ float Bs[BK][BN];

    const int blockRow = blockIdx.y * BM;
    const int blockCol = blockIdx.x * BN;
    const int tx = threadIdx.x & 15;   // 0..15  -> 4 cols each
    const int ty = threadIdx.x >> 4;   // 0..15  -> 4 rows each

    float acc[4][4];
    #pragma unroll
    for (int i = 0; i < 4; i++)
        #pragma unroll
        for (int j = 0; j < 4; j++) acc[i][j] = 0.f;

    for (int k0 = 0; k0 < KD; k0 += BK) {
        // A tile: 64x16, 4 elems/thread (coalesced along kk)
        #pragma unroll
        for (int p = 0; p < 4; p++) {
            int t  = threadIdx.x + p*256;
            int kk = t & 15;
            int ml = t >> 4;
            As[kk][ml] = loadA<MODE>(blockRow + ml, k0 + kk, A0, A1);
        }
        // B tile: 16x64, 4 elems/thread (coalesced along n)
        #pragma unroll
        for (int p = 0; p < 4; p++) {
            int t  = threadIdx.x + p*256;
            int n  = t & 63;
            int kk = t >> 6;
            int gk = k0 + kk;
            Bs[kk][n] = (gk < KD) ? W[(size_t)gk*512 + blockCol + n] : 0.f;
        }
        __syncthreads();

        #pragma unroll
        for (int kk = 0; kk < BK; kk++) {
            float a[4], bb[4];
            #pragma unroll
            for (int i = 0; i < 4; i++) a[i]  = As[kk][ty*4 + i];
            #pragma unroll
            for (int j = 0; j < 4; j++) bb[j] = Bs[kk][tx*4 + j];
            #pragma unroll
            for (int i = 0; i < 4; i++)
                #pragma unroll
                for (int j = 0; j < 4; j++) acc[i][j] = fmaf(a[i], bb[j], acc[i][j]);
        }
        __syncthreads();
    }

    float* C = (MODE == 0) ? g_e : (MODE == 1) ? g_h : Cout;
    #pragma unroll
    for (int i = 0; i < 4; i++) {
        int m = blockRow + ty*4 + i;
        #pragma unroll
        for (int j = 0; j < 4; j++) {
            int n = blockCol + tx*4 + j;
            float x = acc[i][j] + bias[n];
            if (DOSILU) x = siluf(x);
            C[(size_t)m*512 + n] = x;
        }
    }
}

// ---------------------------------------------------------------------------
// Attention + aggregation: per (b,i) block.
// att[j,g] = sigmoid( (1/sqrt(48)) * sum_h q[g*16+h]*k[j,g*16+h] ) * mask[b,i,j]
// a = att / (sum_j att + 1e-6);  agg_v[c] = sum_j a[j, c>>4] * e_value[b,i,j,c]
// v2 = agg_v + self_silu
// ---------------------------------------------------------------------------
__global__ void k_attn(const float* __restrict__ e_mask, const float* __restrict__ e_value)
{
    __shared__ float s_q[512];
    __shared__ float s_att[128*32];
    __shared__ float s_inv[32];

    int m = blockIdx.x;        // b*128+i
    int b = m >> 7;

    for (int c = threadIdx.x; c < 512; c += 256) s_q[c] = g_q[m*512 + c];
    __syncthreads();

    const float scale = 0.14433756729740643f;   // 1/sqrt(48)
    for (int idx = threadIdx.x; idx < 4096; idx += 256) {
        int j = idx >> 5, g = idx & 31;
        const float* kr = &g_k[((b<<7) + j)*512 + (g<<4)];
        float s = 0.f;
        #pragma unroll
        for (int h = 0; h < 16; h++) s = fmaf(s_q[(g<<4) + h], kr[h], s);
        s_att[(j<<5) + g] = sigmf(s * scale) * e_mask[(m<<7) + j];
    }
    __syncthreads();

    if (threadIdx.x < 32) {
        int g = threadIdx.x;
        float s = 0.f;
        #pragma unroll 8
        for (int j = 0; j < 128; j++) s += s_att[(j<<5) + g];
        s_inv[g] = 1.f / (s + 1e-6f);
    }
    __syncthreads();

    for (int c = threadIdx.x; c < 512; c += 256) {
        int g = c >> 4;
        const float* ev = e_value + ((size_t)m*128)*512 + c;
        float acc = 0.f;
        #pragma unroll 4
        for (int j = 0; j < 128; j++) acc = fmaf(s_att[(j<<5) + g], ev[(size_t)j*512], acc);
        g_v2[m*512 + c] = acc * s_inv[g] + g_self[m*512 + c];
    }
}

// ---------------------------------------------------------------------------
// Masked max-pool over nodes: pooled[b,c] = max_i (v2[b,i,c] - 1e9*(1-mask[b,i]))
// ---------------------------------------------------------------------------
__global__ void k_pool(const float* __restrict__ v_mask)
{
    int idx = blockIdx.x*256 + threadIdx.x;
    if (idx >= BB*512) return;
    int b = idx >> 9, c = idx & 511;
    float mx = -3.4e38f;
    for (int i = 0; i < 128; i++) {
        float pen = 1e9f * (1.f - v_mask[(b<<7) + i]);
        mx = fmaxf(mx, g_v2[((b<<7) + i)*512 + c] - pen);
    }
    g_pool[idx] = mx;
}

// ---------------------------------------------------------------------------
// Final: v_out = silu([v2, pooled] @ W_out + b_out)   (512 rows x 256, K=1024)
// ---------------------------------------------------------------------------
__global__ void k_out(const float* __restrict__ W, const float* __restrict__ bias,
                      float* __restrict__ out)
{
    __shared__ float s_in[1024];
    int m = blockIdx.x;
    int b = m >> 7;
    for (int kk = threadIdx.x; kk < 512; kk += 256) {
        s_in[kk]       = g_v2[m*512 + kk];
        s_in[512 + kk] = g_pool[(b<<9) + kk];
    }
    __syncthreads();
    int n = threadIdx.x;
    float acc = bias[n];
    #pragma unroll 4
    for (int kk = 0; kk < 1024; kk++) acc = fmaf(s_in[kk], W[kk*256 + n], acc);
    out[m*256 + n] = siluf(acc);
}

// ---------------------------------------------------------------------------
// Launch
// Inputs (metadata order): 0 v_f, 1 e_f, 2 p_pe, 3 t_pe, 4 e_agg_mask,
// 5 v_agg_mask, 6 W_vpe, 7 b_vpe, 8 W_epe, 9 b_epe, 10 W_ev1, 11 b_ev1,
// 12 W_ev2, 13 b_ev2, 14 W_q, 15 b_q, 16 W_k, 17 b_k, 18 W_self, 19 b_self,
// 20 W_out, 21 b_out
// Output: v_out (4*128*256) then e_value (4*16384*512), float32.
// ---------------------------------------------------------------------------
extern "C" void kernel_launch(void* const* d_in, const int* in_sizes, int n_in,
                              void* d_out, int out_size)
{
    const float* v_f    = (const float*)d_in[0];
    const float* e_f    = (const float*)d_in[1];
    const float* p_pe   = (const float*)d_in[2];
    const float* t_pe   = (const float*)d_in[3];
    const float* e_mask = (const float*)d_in[4];
    const float* v_mask = (const float*)d_in[5];
    const float* W_vpe  = (const float*)d_in[6];
    const float* b_vpe  = (const float*)d_in[7];
    const float* W_epe  = (const float*)d_in[8];
    const float* b_epe  = (const float*)d_in[9];
    const float* W_ev1  = (const float*)d_in[10];
    const float* b_ev1  = (const float*)d_in[11];
    const float* W_ev2  = (const float*)d_in[12];
    const float* b_ev2  = (const float*)d_in[13];
    const float* W_q    = (const float*)d_in[14];
    const float* b_q    = (const float*)d_in[15];
    const float* W_k    = (const float*)d_in[16];
    const float* b_k    = (const float*)d_in[17];
    const float* W_self = (const float*)d_in[18];
    const float* b_self = (const float*)d_in[19];
    const float* W_out  = (const float*)d_in[20];
    const float* b_out  = (const float*)d_in[21];

    float* out_v = (float*)d_out;                       // (4,128,256)
    float* out_e = (float*)d_out + NROWS*V_OUT;         // (4,16384,512)

    dim3 gemm_grid(E_OUT/BN, M_BIG/BM);                 // (8, 1024)

    k_vpe<<<NROWS, 256>>>(v_f, p_pe, t_pe, W_vpe, b_vpe);
    k_qks<<<NROWS, 512>>>(W_q, b_q, W_k, b_k, W_self, b_self);
    gemm_big<0, 612, true ><<<gemm_grid, 256>>>(e_f, t_pe, W_epe, b_epe, nullptr);
    gemm_big<1, 1024, true ><<<gemm_grid, 256>>>(nullptr, nullptr, W_ev1, b_ev1, nullptr);
    gemm_big<2, 512, false><<<gemm_grid, 256>>>(nullptr, nullptr, W_ev2, b_ev2, out_e);
    k_attn<<<NROWS, 256>>>(e_mask, out_e);
    k_pool<<<(BB*512 + 255)/256, 256>>>(v_mask);
    k_out<<<NROWS, 256>>>(W_out, b_out, out_v);
}

// round 3
// speedup vs baseline: 3.2091x; 3.2091x over previous
#include <cuda_runtime.h>
#include <math.h>

// Problem constants
#define BB    4
#define KDIM  128
#define V_IN  256
#define E_IN  512
#define E_OUT 512
#define V_OUT 256
#define P_PE  200
#define T_PE  100
#define NROWS (BB*KDIM)        // 512
#define M_BIG (BB*KDIM*KDIM)   // 65536

// Scratch (device globals -- allocation-free per harness rules)
__device__ float g_v[NROWS*V_IN];
__device__ float g_q[NROWS*E_OUT];
__device__ float g_k[NROWS*E_OUT];
__device__ float g_self[NROWS*E_OUT];
__device__ float g_e[(size_t)M_BIG*E_IN];      // silu(epe)   134 MB
__device__ float g_h[(size_t)M_BIG*E_OUT];     // silu(ev1)   134 MB
__device__ float g_v2[NROWS*E_OUT];
__device__ float g_pool[BB*E_OUT];

__device__ __forceinline__ float siluf(float x){ return x / (1.f + __expf(-x)); }
__device__ __forceinline__ float sigmf(float x){ return 1.f / (1.f + __expf(-x)); }

__device__ __forceinline__ unsigned cvt_tf32(float x){
    unsigned r; asm("cvt.rna.tf32.f32 %0, %1;" : "=r"(r) : "f"(x)); return r;
}

// ===========================================================================
// TF32 mma.sync GEMM: C[M_BIG x 512] = act(gatherA @ W + bias)
// CTA tile 128x128, BK=16, 8 warps (2x4), warp tile 64x32.
// Double-buffered smem; A smem [m][k] pad 20, B smem [k][n] pad 132
// (both conflict-free for the m16n8k8 fragment access pattern).
// MODE 0 (epe): A = [e_f(512)|t_pe(100)], KD=612, silu
// MODE 1 (ev1): A = [v_i(256)|v_j(256)|g_e(512)], KD=1024, silu
// MODE 2 (ev2): A = g_h, KD=512, no act
// ===========================================================================

template<int MODE>
__device__ __forceinline__ float4 ldA4(int m, int k,
                                       const float* __restrict__ A0,
                                       const float* __restrict__ A1,
                                       int b_batch, int i_idx)
{
    if (MODE == 0) {
        if (k < 512) return *(const float4*)&A0[(size_t)m*512 + k];
        float t[4];
        #pragma unroll
        for (int c = 0; c < 4; c++) {
            int r = k + c - 512;
            t[c] = (r < 100) ? A1[b_batch*100 + r] : 0.f;
        }
        return make_float4(t[0], t[1], t[2], t[3]);
    } else if (MODE == 1) {
        if (k < 256)      return *(const float4*)&A0[((b_batch<<7) + i_idx)*256 + k];
        if (k < 512)      return *(const float4*)&A0[((b_batch<<7) + (m & 127))*256 + (k - 256)];
        return *(const float4*)&A1[(size_t)m*512 + (k - 512)];
    } else {
        return *(const float4*)&A0[(size_t)m*512 + k];
    }
}

template<int MODE, int KD, bool DOSILU>
__global__ void __launch_bounds__(256, 2) gemm_mma(
        const float* __restrict__ A0, const float* __restrict__ A1,
        const float* __restrict__ W,  const float* __restrict__ bias,
        float* __restrict__ C)
{
    __shared__ float As[2][128][20];   // [buf][m][k], pad 16->20
    __shared__ float Bs[2][16][132];   // [buf][k][n], pad 128->132

    const int tid  = threadIdx.x;
    const int lane = tid & 31;
    const int wid  = tid >> 5;
    const int g    = lane >> 2;        // 0..7
    const int cq   = lane & 3;         // 0..3
    const int mw   = (wid >> 2) * 64;  // warp M offset
    const int nw   = (wid & 3) * 32;   // warp N offset

    const int blockRow = blockIdx.y * 128;
    const int blockCol = blockIdx.x * 128;
    const int b_batch  = blockRow >> 14;
    const int i_idx    = (blockRow & 16383) >> 7;

    constexpr int NST = (KD + 15) / 16;

    float acc[4][4][4];
    #pragma unroll
    for (int i = 0; i < 4; i++)
        #pragma unroll
        for (int j = 0; j < 4; j++)
            #pragma unroll
            for (int r = 0; r < 4; r++) acc[i][j][r] = 0.f;

    // ---- prologue: stage tile 0 into buf 0
    {
        #pragma unroll
        for (int p = 0; p < 2; p++) {
            int idx = tid + p*256;
            int row = idx >> 2, kq = idx & 3;
            float4 a = ldA4<MODE>(blockRow + row, kq*4, A0, A1, b_batch, i_idx);
            uint4 u = make_uint4(cvt_tf32(a.x), cvt_tf32(a.y), cvt_tf32(a.z), cvt_tf32(a.w));
            *(uint4*)&As[0][row][kq*4] = u;

            int kr = idx >> 5, nq = idx & 31;
            float4 b;
            if (kr < KD) b = *(const float4*)&W[(size_t)kr*512 + blockCol + nq*4];
            else         b = make_float4(0.f,0.f,0.f,0.f);
            uint4 ub = make_uint4(cvt_tf32(b.x), cvt_tf32(b.y), cvt_tf32(b.z), cvt_tf32(b.w));
            *(uint4*)&Bs[0][kr][nq*4] = ub;
        }
    }
    __syncthreads();

    float4 aR[2], bR[2];
    for (int s = 0; s < NST; s++) {
        const int cur = s & 1, nxt = cur ^ 1;

        // prefetch next tile into registers
        if (s + 1 < NST) {
            const int k0n = (s + 1) * 16;
            #pragma unroll
            for (int p = 0; p < 2; p++) {
                int idx = tid + p*256;
                int row = idx >> 2, kq = idx & 3;
                aR[p] = ldA4<MODE>(blockRow + row, k0n + kq*4, A0, A1, b_batch, i_idx);
                int kr = idx >> 5, nq = idx & 31;
                int kg = k0n + kr;
                if (kg < KD) bR[p] = *(const float4*)&W[(size_t)kg*512 + blockCol + nq*4];
                else         bR[p] = make_float4(0.f,0.f,0.f,0.f);
            }
        }

        // compute on current buffer
        #pragma unroll
        for (int kb = 0; kb < 16; kb += 8) {
            unsigned a[4][4], b[4][2];
            #pragma unroll
            for (int ms = 0; ms < 4; ms++) {
                const int r0 = mw + ms*16 + g;
                a[ms][0] = *(const unsigned*)&As[cur][r0    ][kb + cq    ];
                a[ms][1] = *(const unsigned*)&As[cur][r0 + 8][kb + cq    ];
                a[ms][2] = *(const unsigned*)&As[cur][r0    ][kb + cq + 4];
                a[ms][3] = *(const unsigned*)&As[cur][r0 + 8][kb + cq + 4];
            }
            #pragma unroll
            for (int ns = 0; ns < 4; ns++) {
                const int n0 = nw + ns*8 + g;
                b[ns][0] = *(const unsigned*)&Bs[cur][kb + cq    ][n0];
                b[ns][1] = *(const unsigned*)&Bs[cur][kb + cq + 4][n0];
            }
            #pragma unroll
            for (int ms = 0; ms < 4; ms++)
                #pragma unroll
                for (int ns = 0; ns < 4; ns++) {
                    asm volatile(
                        "mma.sync.aligned.m16n8k8.row.col.f32.tf32.tf32.f32 "
                        "{%0,%1,%2,%3}, {%4,%5,%6,%7}, {%8,%9}, {%0,%1,%2,%3};"
                        : "+f"(acc[ms][ns][0]), "+f"(acc[ms][ns][1]),
                          "+f"(acc[ms][ns][2]), "+f"(acc[ms][ns][3])
                        : "r"(a[ms][0]), "r"(a[ms][1]), "r"(a[ms][2]), "r"(a[ms][3]),
                          "r"(b[ns][0]), "r"(b[ns][1]));
                }
        }

        // store prefetched tile into next buffer
        if (s + 1 < NST) {
            #pragma unroll
            for (int p = 0; p < 2; p++) {
                int idx = tid + p*256;
                int row = idx >> 2, kq = idx & 3;
                uint4 u = make_uint4(cvt_tf32(aR[p].x), cvt_tf32(aR[p].y),
                                     cvt_tf32(aR[p].z), cvt_tf32(aR[p].w));
                *(uint4*)&As[nxt][row][kq*4] = u;
                int kr = idx >> 5, nq = idx & 31;
                uint4 ub = make_uint4(cvt_tf32(bR[p].x), cvt_tf32(bR[p].y),
                                      cvt_tf32(bR[p].z), cvt_tf32(bR[p].w));
                *(uint4*)&Bs[nxt][kr][nq*4] = ub;
            }
        }
        __syncthreads();
    }

    // ---- epilogue: bias + activation, float2 stores
    #pragma unroll
    for (int ms = 0; ms < 4; ms++) {
        const int r0 = blockRow + mw + ms*16 + g;
        #pragma unroll
        for (int ns = 0; ns < 4; ns++) {
            const int c0 = blockCol + nw + ns*8 + 2*cq;
            const float bb0 = bias[c0], bb1 = bias[c0 + 1];
            float x0 = acc[ms][ns][0] + bb0;
            float x1 = acc[ms][ns][1] + bb1;
            float x2 = acc[ms][ns][2] + bb0;
            float x3 = acc[ms][ns][3] + bb1;
            if (DOSILU) { x0 = siluf(x0); x1 = siluf(x1); x2 = siluf(x2); x3 = siluf(x3); }
            *(float2*)&C[(size_t)r0*512 + c0]       = make_float2(x0, x1);
            *(float2*)&C[(size_t)(r0+8)*512 + c0]   = make_float2(x2, x3);
        }
    }
}

// ---------------------------------------------------------------------------
// Kernel 1: v = silu([v_f, p_pe, t_pe] @ W_vpe + b)   (512 rows x 256, K=556)
// ---------------------------------------------------------------------------
__global__ void k_vpe(const float* __restrict__ v_f, const float* __restrict__ p_pe,
                      const float* __restrict__ t_pe, const float* __restrict__ W,
                      const float* __restrict__ bias)
{
    __shared__ float s_in[556];
    int m = blockIdx.x;
    int b = m >> 7;
    for (int kk = threadIdx.x; kk < 556; kk += 256) {
        float x;
        if      (kk < 256) x = v_f[m*256 + kk];
        else if (kk < 456) x = p_pe[m*200 + (kk-256)];
        else               x = t_pe[b*100 + (kk-456)];
        s_in[kk] = x;
    }
    __syncthreads();
    int n = threadIdx.x;
    float acc = bias[n];
    #pragma unroll 4
    for (int kk = 0; kk < 556; kk++) acc = fmaf(s_in[kk], W[kk*256 + n], acc);
    g_v[m*256 + n] = siluf(acc);
}

// ---------------------------------------------------------------------------
// Kernel 2: q = v@Wq+b, k = v@Wk+b, self = silu(v@Ws+b)
// ---------------------------------------------------------------------------
__global__ void k_qks(const float* __restrict__ Wq, const float* __restrict__ bq,
                      const float* __restrict__ Wk, const float* __restrict__ bk,
                      const float* __restrict__ Ws, const float* __restrict__ bs)
{
    __shared__ float s_v[256];
    int m = blockIdx.x;
    for (int kk = threadIdx.x; kk < 256; kk += 512) s_v[kk] = g_v[m*256 + kk];
    __syncthreads();
    int n = threadIdx.x;
    float aq = bq[n], ak = bk[n], as_ = bs[n];
    #pragma unroll 4
    for (int kk = 0; kk < 256; kk++) {
        float x = s_v[kk];
        aq  = fmaf(x, Wq[kk*512 + n], aq);
        ak  = fmaf(x, Wk[kk*512 + n], ak);
        as_ = fmaf(x, Ws[kk*512 + n], as_);
    }
    g_q[m*512 + n]    = aq;
    g_k[m*512 + n]    = ak;
    g_self[m*512 + n] = siluf(as_);
}

// ---------------------------------------------------------------------------
// Attention + aggregation
// ---------------------------------------------------------------------------
__global__ void k_attn(const float* __restrict__ e_mask, const float* __restrict__ e_value)
{
    __shared__ float s_q[512];
    __shared__ float s_att[128*32];
    __shared__ float s_inv[32];

    int m = blockIdx.x;
    int b = m >> 7;

    for (int c = threadIdx.x; c < 512; c += 256) s_q[c] = g_q[m*512 + c];
    __syncthreads();

    const float scale = 0.14433756729740643f;   // 1/sqrt(48)
    for (int idx = threadIdx.x; idx < 4096; idx += 256) {
        int j = idx >> 5, g = idx & 31;
        const float* kr = &g_k[((b<<7) + j)*512 + (g<<4)];
        float s = 0.f;
        #pragma unroll
        for (int h = 0; h < 16; h++) s = fmaf(s_q[(g<<4) + h], kr[h], s);
        s_att[(j<<5) + g] = sigmf(s * scale) * e_mask[(m<<7) + j];
    }
    __syncthreads();

    if (threadIdx.x < 32) {
        int g = threadIdx.x;
        float s = 0.f;
        #pragma unroll 8
        for (int j = 0; j < 128; j++) s += s_att[(j<<5) + g];
        s_inv[g] = 1.f / (s + 1e-6f);
    }
    __syncthreads();

    for (int c = threadIdx.x; c < 512; c += 256) {
        int g = c >> 4;
        const float* ev = e_value + ((size_t)m*128)*512 + c;
        float acc = 0.f;
        #pragma unroll 4
        for (int j = 0; j < 128; j++) acc = fmaf(s_att[(j<<5) + g], ev[(size_t)j*512], acc);
        g_v2[m*512 + c] = acc * s_inv[g] + g_self[m*512 + c];
    }
}

__global__ void k_pool(const float* __restrict__ v_mask)
{
    int idx = blockIdx.x*256 + threadIdx.x;
    if (idx >= BB*512) return;
    int b = idx >> 9, c = idx & 511;
    float mx = -3.4e38f;
    for (int i = 0; i < 128; i++) {
        float pen = 1e9f * (1.f - v_mask[(b<<7) + i]);
        mx = fmaxf(mx, g_v2[((b<<7) + i)*512 + c] - pen);
    }
    g_pool[idx] = mx;
}

__global__ void k_out(const float* __restrict__ W, const float* __restrict__ bias,
                      float* __restrict__ out)
{
    __shared__ float s_in[1024];
    int m = blockIdx.x;
    int b = m >> 7;
    for (int kk = threadIdx.x; kk < 512; kk += 256) {
        s_in[kk]       = g_v2[m*512 + kk];
        s_in[512 + kk] = g_pool[(b<<9) + kk];
    }
    __syncthreads();
    int n = threadIdx.x;
    float acc = bias[n];
    #pragma unroll 4
    for (int kk = 0; kk < 1024; kk++) acc = fmaf(s_in[kk], W[kk*256 + n], acc);
    out[m*256 + n] = siluf(acc);
}

// ---------------------------------------------------------------------------
// Launch
// ---------------------------------------------------------------------------
extern "C" void kernel_launch(void* const* d_in, const int* in_sizes, int n_in,
                              void* d_out, int out_size)
{
    const float* v_f    = (const float*)d_in[0];
    const float* e_f    = (const float*)d_in[1];
    const float* p_pe   = (const float*)d_in[2];
    const float* t_pe   = (const float*)d_in[3];
    const float* e_mask = (const float*)d_in[4];
    const float* v_mask = (const float*)d_in[5];
    const float* W_vpe  = (const float*)d_in[6];
    const float* b_vpe  = (const float*)d_in[7];
    const float* W_epe  = (const float*)d_in[8];
    const float* b_epe  = (const float*)d_in[9];
    const float* W_ev1  = (const float*)d_in[10];
    const float* b_ev1  = (const float*)d_in[11];
    const float* W_ev2  = (const float*)d_in[12];
    const float* b_ev2  = (const float*)d_in[13];
    const float* W_q    = (const float*)d_in[14];
    const float* b_q    = (const float*)d_in[15];
    const float* W_k    = (const float*)d_in[16];
    const float* b_k    = (const float*)d_in[17];
    const float* W_self = (const float*)d_in[18];
    const float* b_self = (const float*)d_in[19];
    const float* W_out  = (const float*)d_in[20];
    const float* b_out  = (const float*)d_in[21];

    float* out_v = (float*)d_out;                       // (4,128,256)
    float* out_e = (float*)d_out + NROWS*V_OUT;         // (4,16384,512)

    float *pe, *ph, *pv;
    cudaGetSymbolAddress((void**)&pe, g_e);
    cudaGetSymbolAddress((void**)&ph, g_h);
    cudaGetSymbolAddress((void**)&pv, g_v);

    dim3 gemm_grid(4, M_BIG/128);                       // (4, 512)

    k_vpe<<<NROWS, 256>>>(v_f, p_pe, t_pe, W_vpe, b_vpe);
    k_qks<<<NROWS, 512>>>(W_q, b_q, W_k, b_k, W_self, b_self);
    gemm_mma<0, 612, true ><<<gemm_grid, 256>>>(e_f, t_pe, W_epe, b_epe, pe);
    gemm_mma<1, 1024, true ><<<gemm_grid, 256>>>(pv, pe, W_ev1, b_ev1, ph);
    gemm_mma<2, 512, false><<<gemm_grid, 256>>>(ph, nullptr, W_ev2, b_ev2, out_e);
    k_attn<<<NROWS, 256>>>(e_mask, out_e);
    k_pool<<<(BB*512 + 255)/256, 256>>>(v_mask);
    k_out<<<NROWS, 256>>>(W_out, b_out, out_v);
}

// round 5
// speedup vs baseline: 3.9620x; 1.2346x over previous
#include <cuda_runtime.h>
#include <cuda_fp16.h>
#include <math.h>

// Problem constants
#define BB    4
#define KDIM  128
#define V_IN  256
#define E_IN  512
#define E_OUT 512
#define V_OUT 256
#define P_PE  200
#define T_PE  100
#define NROWS (BB*KDIM)        // 512
#define M_BIG (BB*KDIM*KDIM)   // 65536

// Scratch (device globals -- allocation-free per harness rules)
__device__ float g_v[NROWS*V_IN];
__device__ float g_q[NROWS*E_OUT];
__device__ float g_k[NROWS*E_OUT];
__device__ float g_self[NROWS*E_OUT];
__device__ float g_e[(size_t)M_BIG*E_IN];      // silu(epe)   134 MB
__device__ float g_h[(size_t)M_BIG*E_OUT];     // silu(ev1)   134 MB
__device__ float g_v2[NROWS*E_OUT];
__device__ float g_pool[BB*E_OUT];

__device__ __forceinline__ float siluf(float x){ return x / (1.f + __expf(-x)); }
__device__ __forceinline__ float sigmf(float x){ return 1.f / (1.f + __expf(-x)); }

__device__ __forceinline__ unsigned smem_u32(const void* p){
    unsigned r;
    asm("{ .reg .u64 t; cvta.to.shared.u64 t, %1; cvt.u32.u64 %0, t; }" : "=r"(r) : "l"(p));
    return r;
}
__device__ __forceinline__ unsigned pack2h(float x, float y){
    __half2 h = __floats2half2_rn(x, y);
    return *(unsigned*)&h;
}

// ===========================================================================
// FP16 mma.sync GEMM (fp32 accumulate): C[M_BIG x 512] = act(gatherA @ W + b)
// CTA tile 128x128, BK=32, 8 warps (2x4), warp tile 64x32.
// A smem [m][k] halves, row stride 40 (80B, 16B-aligned, ldmatrix conflict-free)
// B smem [k][n] halves, row stride 136 (272B, conflict-free), ldmatrix.trans
// Double-buffered, register-staged global prefetch.
// MODE 0 (epe): A = [e_f(512)|t_pe(100)], KD=612, silu
// MODE 1 (ev1): A = [v_i(256)|v_j(256)|g_e(512)], KD=1024, silu
// MODE 2 (ev2): A = g_h, KD=512, no act
// ===========================================================================
#define ASTRIDE 40
#define BSTRIDE 136
#define ABUF (128*ASTRIDE)     // halves per A buffer
#define BBUF (32*BSTRIDE)      // halves per B buffer

template<int MODE>
__device__ __forceinline__ float4 ldA4(int m, int k,
                                       const float* __restrict__ A0,
                                       const float* __restrict__ A1,
                                       int b_batch, int i_idx)
{
    if (MODE == 0) {
        if (k < 512) return *(const float4*)&A0[(size_t)m*512 + k];
        float t[4];
        #pragma unroll
        for (int c = 0; c < 4; c++) {
            int r = k + c - 512;
            t[c] = (r < 100) ? A1[b_batch*100 + r] : 0.f;
        }
        return make_float4(t[0], t[1], t[2], t[3]);
    } else if (MODE == 1) {
        if (k < 256)      return *(const float4*)&A0[((b_batch<<7) + i_idx)*256 + k];
        if (k < 512)      return *(const float4*)&A0[((b_batch<<7) + (m & 127))*256 + (k - 256)];
        return *(const float4*)&A1[(size_t)m*512 + (k - 512)];
    } else {
        return *(const float4*)&A0[(size_t)m*512 + k];
    }
}

template<int MODE, int KD, bool DOSILU>
__global__ void __launch_bounds__(256, 2) gemm_mma(
        const float* __restrict__ A0, const float* __restrict__ A1,
        const float* __restrict__ W,  const float* __restrict__ bias,
        float* __restrict__ C)
{
    __shared__ __half As[2*ABUF];
    __shared__ __half Bs[2*BBUF];

    const int tid  = threadIdx.x;
    const int lane = tid & 31;
    const int wid  = tid >> 5;
    const int g    = lane >> 2;
    const int cq   = lane & 3;
    const int mw   = (wid >> 2) * 64;
    const int nw   = (wid & 3) * 32;

    const int blockRow = blockIdx.y * 128;
    const int blockCol = blockIdx.x * 128;
    const int b_batch  = blockRow >> 14;
    const int i_idx    = (blockRow & 16383) >> 7;

    constexpr int NST = (KD + 31) / 32;

    // staging coords
    const int arow = tid >> 1;             // 0..127
    const int aks  = (tid & 1) * 16;       // 0 / 16
    const int bk   = tid >> 3;             // 0..31
    const int bn0  = (tid & 7) * 16;       // 0..112

    const unsigned sA = smem_u32(As);
    const unsigned sB = smem_u32(Bs);

    // ldmatrix per-lane address components
    const int rowA_l = lane & 15;
    const int kA_l   = (lane >> 4) << 3;
    const int rowB_l = (lane & 7) + ((lane >> 3) & 1) * 8;
    const int nB_l   = (lane >> 4) << 3;

    float acc[4][4][4];
    #pragma unroll
    for (int i = 0; i < 4; i++)
        #pragma unroll
        for (int j = 0; j < 4; j++)
            #pragma unroll
            for (int r = 0; r < 4; r++) acc[i][j][r] = 0.f;

    // ---- prologue: stage tile 0 into buf 0
    {
        #pragma unroll
        for (int j = 0; j < 2; j++) {
            float4 a0 = ldA4<MODE>(blockRow + arow, aks + 8*j,     A0, A1, b_batch, i_idx);
            float4 a1 = ldA4<MODE>(blockRow + arow, aks + 8*j + 4, A0, A1, b_batch, i_idx);
            uint4 u = make_uint4(pack2h(a0.x,a0.y), pack2h(a0.z,a0.w),
                                 pack2h(a1.x,a1.y), pack2h(a1.z,a1.w));
            *(uint4*)&As[arow*ASTRIDE + aks + 8*j] = u;
        }
        #pragma unroll
        for (int j = 0; j < 2; j++) {
            float4 b0, b1;
            if (bk < KD) {
                b0 = *(const float4*)&W[(size_t)bk*512 + blockCol + bn0 + 8*j];
                b1 = *(const float4*)&W[(size_t)bk*512 + blockCol + bn0 + 8*j + 4];
            } else { b0 = b1 = make_float4(0.f,0.f,0.f,0.f); }
            uint4 u = make_uint4(pack2h(b0.x,b0.y), pack2h(b0.z,b0.w),
                                 pack2h(b1.x,b1.y), pack2h(b1.z,b1.w));
            *(uint4*)&Bs[bk*BSTRIDE + bn0 + 8*j] = u;
        }
    }
    __syncthreads();

    float4 aR[4], bR[4];
    for (int s = 0; s < NST; s++) {
        const int cur = s & 1, nxt = cur ^ 1;

        // prefetch next tile into registers
        if (s + 1 < NST) {
            const int k0n = (s + 1) * 32;
            #pragma unroll
            for (int j = 0; j < 4; j++)
                aR[j] = ldA4<MODE>(blockRow + arow, k0n + aks + 4*j, A0, A1, b_batch, i_idx);
            const int kg = k0n + bk;
            if (kg < KD) {
                #pragma unroll
                for (int j = 0; j < 4; j++)
                    bR[j] = *(const float4*)&W[(size_t)kg*512 + blockCol + bn0 + 4*j];
            } else {
                #pragma unroll
                for (int j = 0; j < 4; j++) bR[j] = make_float4(0.f,0.f,0.f,0.f);
            }
        }

        // compute on current buffer: 2 ksteps of k16
        const unsigned baseA = sA + cur*(ABUF*2);
        const unsigned baseB = sB + cur*(BBUF*2);
        #pragma unroll
        for (int kb = 0; kb < 32; kb += 16) {
            unsigned a[4][4], b[2][4];
            #pragma unroll
            for (int ms = 0; ms < 4; ms++) {
                unsigned addr = baseA + ((mw + ms*16 + rowA_l)*ASTRIDE + kb + kA_l)*2;
                asm volatile("ldmatrix.sync.aligned.m8n8.x4.shared.b16 {%0,%1,%2,%3}, [%4];"
                    : "=r"(a[ms][0]), "=r"(a[ms][1]), "=r"(a[ms][2]), "=r"(a[ms][3])
                    : "r"(addr));
            }
            #pragma unroll
            for (int ng = 0; ng < 2; ng++) {
                unsigned addr = baseB + ((kb + rowB_l)*BSTRIDE + nw + ng*16 + nB_l)*2;
                asm volatile("ldmatrix.sync.aligned.m8n8.x4.trans.shared.b16 {%0,%1,%2,%3}, [%4];"
                    : "=r"(b[ng][0]), "=r"(b[ng][1]), "=r"(b[ng][2]), "=r"(b[ng][3])
                    : "r"(addr));
            }
            #pragma unroll
            for (int ms = 0; ms < 4; ms++)
                #pragma unroll
                for (int ng = 0; ng < 2; ng++)
                    #pragma unroll
                    for (int h = 0; h < 2; h++) {
                        float* c = acc[ms][ng*2 + h];
                        asm volatile(
                            "mma.sync.aligned.m16n8k16.row.col.f32.f16.f16.f32 "
                            "{%0,%1,%2,%3}, {%4,%5,%6,%7}, {%8,%9}, {%0,%1,%2,%3};"
                            : "+f"(c[0]), "+f"(c[1]), "+f"(c[2]), "+f"(c[3])
                            : "r"(a[ms][0]), "r"(a[ms][1]), "r"(a[ms][2]), "r"(a[ms][3]),
                              "r"(b[ng][2*h]), "r"(b[ng][2*h+1]));
                    }
        }

        // store prefetched tile into next buffer
        if (s + 1 < NST) {
            #pragma unroll
            for (int j = 0; j < 2; j++) {
                uint4 u = make_uint4(pack2h(aR[2*j].x, aR[2*j].y), pack2h(aR[2*j].z, aR[2*j].w),
                                     pack2h(aR[2*j+1].x, aR[2*j+1].y), pack2h(aR[2*j+1].z, aR[2*j+1].w));
                *(uint4*)&As[nxt*ABUF + arow*ASTRIDE + aks + 8*j] = u;
            }
            #pragma unroll
            for (int j = 0; j < 2; j++) {
                uint4 u = make_uint4(pack2h(bR[2*j].x, bR[2*j].y), pack2h(bR[2*j].z, bR[2*j].w),
                                     pack2h(bR[2*j+1].x, bR[2*j+1].y), pack2h(bR[2*j+1].z, bR[2*j+1].w));
                *(uint4*)&Bs[nxt*BBUF + bk*BSTRIDE + bn0 + 8*j] = u;
            }
        }
        __syncthreads();
    }

    // ---- epilogue: bias + activation, float2 stores
    #pragma unroll
    for (int ms = 0; ms < 4; ms++) {
        const int r0 = blockRow + mw + ms*16 + g;
        #pragma unroll
        for (int ns = 0; ns < 4; ns++) {
            const int c0 = blockCol + nw + ns*8 + 2*cq;
            const float bb0 = bias[c0], bb1 = bias[c0 + 1];
            float x0 = acc[ms][ns][0] + bb0;
            float x1 = acc[ms][ns][1] + bb1;
            float x2 = acc[ms][ns][2] + bb0;
            float x3 = acc[ms][ns][3] + bb1;
            if (DOSILU) { x0 = siluf(x0); x1 = siluf(x1); x2 = siluf(x2); x3 = siluf(x3); }
            *(float2*)&C[(size_t)r0*512 + c0]       = make_float2(x0, x1);
            *(float2*)&C[(size_t)(r0+8)*512 + c0]   = make_float2(x2, x3);
        }
    }
}

// ---------------------------------------------------------------------------
// Kernel 1: v = silu([v_f, p_pe, t_pe] @ W_vpe + b)   (512 rows x 256, K=556)
// ---------------------------------------------------------------------------
__global__ void k_vpe(const float* __restrict__ v_f, const float* __restrict__ p_pe,
                      const float* __restrict__ t_pe, const float* __restrict__ W,
                      const float* __restrict__ bias)
{
    __shared__ float s_in[556];
    int m = blockIdx.x;
    int b = m >> 7;
    for (int kk = threadIdx.x; kk < 556; kk += 256) {
        float x;
        if      (kk < 256) x = v_f[m*256 + kk];
        else if (kk < 456) x = p_pe[m*200 + (kk-256)];
        else               x = t_pe[b*100 + (kk-456)];
        s_in[kk] = x;
    }
    __syncthreads();
    int n = threadIdx.x;
    float acc = bias[n];
    #pragma unroll 4
    for (int kk = 0; kk < 556; kk++) acc = fmaf(s_in[kk], W[kk*256 + n], acc);
    g_v[m*256 + n] = siluf(acc);
}

// ---------------------------------------------------------------------------
// Kernel 2: q = v@Wq+b, k = v@Wk+b, self = silu(v@Ws+b)
// ---------------------------------------------------------------------------
__global__ void k_qks(const float* __restrict__ Wq, const float* __restrict__ bq,
                      const float* __restrict__ Wk, const float* __restrict__ bk,
                      const float* __restrict__ Ws, const float* __restrict__ bs)
{
    __shared__ float s_v[256];
    int m = blockIdx.x;
    for (int kk = threadIdx.x; kk < 256; kk += 512) s_v[kk] = g_v[m*256 + kk];
    __syncthreads();
    int n = threadIdx.x;
    float aq = bq[n], ak = bk[n], as_ = bs[n];
    #pragma unroll 4
    for (int kk = 0; kk < 256; kk++) {
        float x = s_v[kk];
        aq  = fmaf(x, Wq[kk*512 + n], aq);
        ak  = fmaf(x, Wk[kk*512 + n], ak);
        as_ = fmaf(x, Ws[kk*512 + n], as_);
    }
    g_q[m*512 + n]    = aq;
    g_k[m*512 + n]    = ak;
    g_self[m*512 + n] = siluf(as_);
}

// ---------------------------------------------------------------------------
// Attention + aggregation
// ---------------------------------------------------------------------------
__global__ void k_attn(const float* __restrict__ e_mask, const float* __restrict__ e_value)
{
    __shared__ float s_q[512];
    __shared__ float s_att[128*32];
    __shared__ float s_inv[32];

    int m = blockIdx.x;
    int b = m >> 7;

    for (int c = threadIdx.x; c < 512; c += 256) s_q[c] = g_q[m*512 + c];
    __syncthreads();

    const float scale = 0.14433756729740643f;   // 1/sqrt(48)
    for (int idx = threadIdx.x; idx < 4096; idx += 256) {
        int j = idx >> 5, g = idx & 31;
        const float* kr = &g_k[((b<<7) + j)*512 + (g<<4)];
        float s = 0.f;
        #pragma unroll
        for (int h = 0; h < 16; h++) s = fmaf(s_q[(g<<4) + h], kr[h], s);
        s_att[(j<<5) + g] = sigmf(s * scale) * e_mask[(m<<7) + j];
    }
    __syncthreads();

    if (threadIdx.x < 32) {
        int g = threadIdx.x;
        float s = 0.f;
        #pragma unroll 8
        for (int j = 0; j < 128; j++) s += s_att[(j<<5) + g];
        s_inv[g] = 1.f / (s + 1e-6f);
    }
    __syncthreads();

    for (int c = threadIdx.x; c < 512; c += 256) {
        int g = c >> 4;
        const float* ev = e_value + ((size_t)m*128)*512 + c;
        float acc = 0.f;
        #pragma unroll 4
        for (int j = 0; j < 128; j++) acc = fmaf(s_att[(j<<5) + g], ev[(size_t)j*512], acc);
        g_v2[m*512 + c] = acc * s_inv[g] + g_self[m*512 + c];
    }
}

__global__ void k_pool(const float* __restrict__ v_mask)
{
    int idx = blockIdx.x*256 + threadIdx.x;
    if (idx >= BB*512) return;
    int b = idx >> 9, c = idx & 511;
    float mx = -3.4e38f;
    for (int i = 0; i < 128; i++) {
        float pen = 1e9f * (1.f - v_mask[(b<<7) + i]);
        mx = fmaxf(mx, g_v2[((b<<7) + i)*512 + c] - pen);
    }
    g_pool[idx] = mx;
}

__global__ void k_out(const float* __restrict__ W, const float* __restrict__ bias,
                      float* __restrict__ out)
{
    __shared__ float s_in[1024];
    int m = blockIdx.x;
    int b = m >> 7;
    for (int kk = threadIdx.x; kk < 512; kk += 256) {
        s_in[kk]       = g_v2[m*512 + kk];
        s_in[512 + kk] = g_pool[(b<<9) + kk];
    }
    __syncthreads();
    int n = threadIdx.x;
    float acc = bias[n];
    #pragma unroll 4
    for (int kk = 0; kk < 1024; kk++) acc = fmaf(s_in[kk], W[kk*256 + n], acc);
    out[m*256 + n] = siluf(acc);
}

// ---------------------------------------------------------------------------
// Launch
// ---------------------------------------------------------------------------
extern "C" void kernel_launch(void* const* d_in, const int* in_sizes, int n_in,
                              void* d_out, int out_size)
{
    const float* v_f    = (const float*)d_in[0];
    const float* e_f    = (const float*)d_in[1];
    const float* p_pe   = (const float*)d_in[2];
    const float* t_pe   = (const float*)d_in[3];
    const float* e_mask = (const float*)d_in[4];
    const float* v_mask = (const float*)d_in[5];
    const float* W_vpe  = (const float*)d_in[6];
    const float* b_vpe  = (const float*)d_in[7];
    const float* W_epe  = (const float*)d_in[8];
    const float* b_epe  = (const float*)d_in[9];
    const float* W_ev1  = (const float*)d_in[10];
    const float* b_ev1  = (const float*)d_in[11];
    const float* W_ev2  = (const float*)d_in[12];
    const float* b_ev2  = (const float*)d_in[13];
    const float* W_q    = (const float*)d_in[14];
    const float* b_q    = (const float*)d_in[15];
    const float* W_k    = (const float*)d_in[16];
    const float* b_k    = (const float*)d_in[17];
    const float* W_self = (const float*)d_in[18];
    const float* b_self = (const float*)d_in[19];
    const float* W_out  = (const float*)d_in[20];
    const float* b_out  = (const float*)d_in[21];

    float* out_v = (float*)d_out;                       // (4,128,256)
    float* out_e = (float*)d_out + NROWS*V_OUT;         // (4,16384,512)

    float *pe, *ph, *pv;
    cudaGetSymbolAddress((void**)&pe, g_e);
    cudaGetSymbolAddress((void**)&ph, g_h);
    cudaGetSymbolAddress((void**)&pv, g_v);

    dim3 gemm_grid(4, M_BIG/128);                       // (4, 512)

    k_vpe<<<NROWS, 256>>>(v_f, p_pe, t_pe, W_vpe, b_vpe);
    k_qks<<<NROWS, 512>>>(W_q, b_q, W_k, b_k, W_self, b_self);
    gemm_mma<0, 612, true ><<<gemm_grid, 256>>>(e_f, t_pe, W_epe, b_epe, pe);
    gemm_mma<1, 1024, true ><<<gemm_grid, 256>>>(pv, pe, W_ev1, b_ev1, ph);
    gemm_mma<2, 512, false><<<gemm_grid, 256>>>(ph, nullptr, W_ev2, b_ev2, out_e);
    k_attn<<<NROWS, 256>>>(e_mask, out_e);
    k_pool<<<(BB*512 + 255)/256, 256>>>(v_mask);
    k_out<<<NROWS, 256>>>(W_out, b_out, out_v);
}